// round 6
// baseline (speedup 1.0000x reference)
#include <cuda_runtime.h>
#include <math.h>

#define FULL_MASK 0xFFFFFFFFu

// ---------------- problem constants ----------------
constexpr int DIM = 128;
constexpr int VOX = DIM * DIM * DIM;          // 2,097,152 per volume
constexpr double OMEGA_F = 12582912.0;        // (2,3,128^3)
constexpr double OMEGA_I = 4194304.0;         // (2,1,128^3)

// ---------------- LCC tile geometry ----------------
constexpr int TX = 32, TY = 8, TZ = 8;        // interior tile
constexpr int LY = TY + 4, LZ = TZ + 4;       // 12, 12 (halo 2 each side)
constexpr int AROWS = LZ * LY;                // 144 rows of 36 (x with halo)
constexpr int ASTR = 37;                      // padded row stride (odd -> conflict-free)
constexpr int BSTR = 33;                      // padded 32-wide rows
constexpr int A_SZ = AROWS * ASTR;            // 5328
constexpr int B_SZ = AROWS * BSTR;            // 4752
constexpr int C_SZ = LZ * TY * BSTR;          // 3168
constexpr int SMEM_FLOATS = 2 * (A_SZ + B_SZ + C_SZ);   // 26496
constexpr int SMEM_BYTES  = SMEM_FLOATS * 4;            // 105984 -> 2 CTAs/SM

// tiles: 4 (x) * 16 (y) * 16 (z) * 2 volumes * 2 pairs = 4096
// reduction blocks: 3 jobs * 1024 = 3072. total grid = 7168 = 7 * 1024
constexpr int GRID_X = 7168;
constexpr int RED_BLOCKS_PER_JOB = 1024;
constexpr int NTHREADS = 256;

// accumulators (doubles):
// [0]      sum (F0-F0g)^2
// [1..3]   pair0: sum dg*dp, sum dg^2, sum dp^2
// [4..6]   pair1: same
// [7],[8]  tversky0: sum g*p, sum (g+p)
// [9],[10] tversky1: same
// [11]     dummy sink
__device__ double g_acc[12];

__global__ void init_kernel() {
    if (threadIdx.x < 12) g_acc[threadIdx.x] = 0.0;
}

__device__ __forceinline__ void block_reduce_add3(float a, float b, float c,
                                                  double* d0, double* d1, double* d2) {
    __shared__ float red[3][8];
    #pragma unroll
    for (int o = 16; o > 0; o >>= 1) {
        a += __shfl_down_sync(FULL_MASK, a, o);
        b += __shfl_down_sync(FULL_MASK, b, o);
        c += __shfl_down_sync(FULL_MASK, c, o);
    }
    int w = threadIdx.x >> 5, l = threadIdx.x & 31;
    if (l == 0) { red[0][w] = a; red[1][w] = b; red[2][w] = c; }
    __syncthreads();
    if (w == 0) {
        a = (l < 8) ? red[0][l] : 0.f;
        b = (l < 8) ? red[1][l] : 0.f;
        c = (l < 8) ? red[2][l] : 0.f;
        #pragma unroll
        for (int o = 4; o > 0; o >>= 1) {
            a += __shfl_down_sync(FULL_MASK, a, o);
            b += __shfl_down_sync(FULL_MASK, b, o);
            c += __shfl_down_sync(FULL_MASK, c, o);
        }
        if (l == 0) {
            atomicAdd(d0, (double)a);
            atomicAdd(d1, (double)b);
            atomicAdd(d2, (double)c);
        }
    }
}

__global__ void __launch_bounds__(NTHREADS, 2)
main_kernel(const float* __restrict__ F0,  const float* __restrict__ F0g,
            const float* __restrict__ I0,  const float* __restrict__ I0R,
            const float* __restrict__ I1,  const float* __restrict__ I1R,
            const float* __restrict__ S0,  const float* __restrict__ S0g,
            const float* __restrict__ S1,  const float* __restrict__ S1g) {
    extern __shared__ float sm[];
    const int tid = threadIdx.x;
    const int bid = blockIdx.x;
    const int q = bid / 7;
    const int r = bid - q * 7;

    if ((r & 1) == 0) {
        // ---------------- LCC tile block ----------------
        int tile = (r >> 1) * 1024 + q;   // [0, 4096)
        int tx_ = tile & 3;  int t = tile >> 2;
        int ty_ = t & 15;    t >>= 4;
        int tz_ = t & 15;    t >>= 4;
        int vol  = t & 1;
        int pair = t >> 1;

        const float* gt = (pair == 0 ? I0  : I1)  + vol * VOX;
        const float* pr = (pair == 0 ? I0R : I1R) + vol * VOX;
        const int x0 = tx_ * TX, y0 = ty_ * TY, z0 = tz_ * TZ;

        float* Ag = sm;
        float* Ap = Ag + A_SZ;
        float* Bg = Ap + A_SZ;
        float* Bp = Bg + B_SZ;
        float* Cg = Bp + B_SZ;
        float* Cp = Cg + C_SZ;

        // ---- load tile + halo (zero padding outside volume) ----
        for (int i = tid; i < AROWS * 36; i += NTHREADS) {
            int k   = i % 36;
            int row = i / 36;
            int ly = row % LY, lz = row / LY;
            int gx = x0 + k - 2, gy = y0 + ly - 2, gz = z0 + lz - 2;
            float vg = 0.f, vp = 0.f;
            if ((unsigned)gx < 128u && (unsigned)gy < 128u && (unsigned)gz < 128u) {
                int idx = (gz * DIM + gy) * DIM + gx;
                vg = __ldg(gt + idx);
                vp = __ldg(pr + idx);
            }
            Ag[row * ASTR + k] = vg;
            Ap[row * ASTR + k] = vp;
        }
        __syncthreads();

        // ---- x-pass: 5-tap running sum per row (144 rows) ----
        if (tid < AROWS) {
            const float* ag = Ag + tid * ASTR;
            const float* ap = Ap + tid * ASTR;
            float* bg = Bg + tid * BSTR;
            float* bp = Bp + tid * BSTR;
            float sg = ag[0] + ag[1] + ag[2] + ag[3];
            float sp = ap[0] + ap[1] + ap[2] + ap[3];
            #pragma unroll
            for (int x = 0; x < TX; x++) {
                sg += ag[x + 4]; sp += ap[x + 4];
                bg[x] = sg;      bp[x] = sp;
                sg -= ag[x];     sp -= ap[x];
            }
        }
        __syncthreads();

        // ---- y-pass: running sum down y for (z, x) columns (12*32 = 384) ----
        for (int tk = tid; tk < LZ * TX; tk += NTHREADS) {
            int x = tk & 31, z = tk >> 5;
            const float* bg = Bg + z * LY * BSTR + x;
            const float* bp = Bp + z * LY * BSTR + x;
            float* cg = Cg + z * TY * BSTR + x;
            float* cp = Cp + z * TY * BSTR + x;
            float sg = bg[0] + bg[BSTR] + bg[2 * BSTR] + bg[3 * BSTR];
            float sp = bp[0] + bp[BSTR] + bp[2 * BSTR] + bp[3 * BSTR];
            #pragma unroll
            for (int y = 0; y < TY; y++) {
                sg += bg[(y + 4) * BSTR]; sp += bp[(y + 4) * BSTR];
                cg[y * BSTR] = sg;        cp[y * BSTR] = sp;
                sg -= bg[y * BSTR];       sp -= bp[y * BSTR];
            }
        }
        __syncthreads();

        // ---- z-pass + finalize: 256 threads <-> 8x32 (dy,dx) columns ----
        {
            const int dx = tid & 31, dy = tid >> 5;
            const float* cg = Cg + dy * BSTR + dx;
            const float* cp = Cp + dy * BSTR + dx;
            constexpr int CZ = TY * BSTR;   // z stride in C
            float sg = cg[0] + cg[CZ] + cg[2 * CZ] + cg[3 * CZ];
            float sp = cp[0] + cp[CZ] + cp[2 * CZ] + cp[3 * CZ];
            float s_gp = 0.f, s_gg = 0.f, s_pp = 0.f;
            constexpr float INV125 = 1.0f / 125.0f;
            #pragma unroll
            for (int dz = 0; dz < TZ; dz++) {
                sg += cg[(dz + 4) * CZ];
                sp += cp[(dz + 4) * CZ];
                int aidx = ((dz + 2) * LY + dy + 2) * ASTR + dx + 2;
                float og = Ag[aidx];
                float op = Ap[aidx];
                float dg = og - sg * INV125;
                float dp = op - sp * INV125;
                s_gp += dg * dp;
                s_gg += dg * dg;
                s_pp += dp * dp;
                sg -= cg[dz * CZ];
                sp -= cp[dz * CZ];
            }
            block_reduce_add3(s_gp, s_gg, s_pp,
                              &g_acc[1 + 3 * pair], &g_acc[2 + 3 * pair], &g_acc[3 + 3 * pair]);
        }
    } else {
        // ---------------- streaming reduction block ----------------
        int job = r >> 1;            // 0: F L2, 1: tversky0, 2: tversky1
        int jb  = q;                 // [0, 1024)
        const float4 *a4, *b4;
        int n4;
        if (job == 0) { a4 = (const float4*)F0; b4 = (const float4*)F0g; n4 = (6 * VOX) / 4; }
        else if (job == 1) { a4 = (const float4*)S0; b4 = (const float4*)S0g; n4 = (2 * VOX) / 4; }
        else { a4 = (const float4*)S1; b4 = (const float4*)S1g; n4 = (2 * VOX) / 4; }

        float acc1 = 0.f, acc2 = 0.f;
        const int stride = RED_BLOCKS_PER_JOB * NTHREADS;
        if (job == 0) {
            for (int i = jb * NTHREADS + tid; i < n4; i += stride) {
                float4 x = __ldg(a4 + i), y = __ldg(b4 + i);
                float d0 = x.x - y.x, d1 = x.y - y.y, d2 = x.z - y.z, d3 = x.w - y.w;
                acc1 += d0 * d0 + d1 * d1 + d2 * d2 + d3 * d3;
            }
            block_reduce_add3(acc1, 0.f, 0.f, &g_acc[0], &g_acc[11], &g_acc[11]);
        } else {
            for (int i = jb * NTHREADS + tid; i < n4; i += stride) {
                float4 x = __ldg(a4 + i), y = __ldg(b4 + i);
                acc1 += x.x * y.x + x.y * y.y + x.z * y.z + x.w * y.w;
                acc2 += (x.x + y.x) + (x.y + y.y) + (x.z + y.z) + (x.w + y.w);
            }
            block_reduce_add3(acc1, acc2, 0.f,
                              &g_acc[5 + 2 * job], &g_acc[6 + 2 * job], &g_acc[11]);
        }
    }
}

__global__ void finalize_kernel(float* __restrict__ out) {
    double total = sqrt(g_acc[0]) / OMEGA_F;             // reg_field_loss
    #pragma unroll
    for (int p = 0; p < 2; p++) {                         // LAMBDA * lcc
        double num = g_acc[1 + 3 * p]; num *= num;
        double den = g_acc[2 + 3 * p] * g_acc[3 + 3 * p];
        if (den < 1e-5) den = 1e-5;
        total += 10.0 * (-(num / den) / OMEGA_I);
    }
    #pragma unroll
    for (int t = 0; t < 2; t++) {                         // BETA * tversky
        double den = g_acc[8 + 2 * t];
        if (den < 1e-5) den = 1e-5;
        total += 10.0 * (-(g_acc[7 + 2 * t] / den));
    }
    out[0] = (float)total;
}

extern "C" void kernel_launch(void* const* d_in, const int* in_sizes, int n_in,
                              void* d_out, int out_size) {
    const float* F0  = (const float*)d_in[0];
    const float* F0g = (const float*)d_in[1];
    const float* I0  = (const float*)d_in[2];
    const float* I0R = (const float*)d_in[3];
    const float* I1  = (const float*)d_in[4];
    const float* I1R = (const float*)d_in[5];
    const float* S0  = (const float*)d_in[6];
    const float* S0g = (const float*)d_in[7];
    const float* S1  = (const float*)d_in[8];
    const float* S1g = (const float*)d_in[9];

    static bool attr_set = false;
    if (!attr_set) {
        cudaFuncSetAttribute(main_kernel, cudaFuncAttributeMaxDynamicSharedMemorySize, SMEM_BYTES);
        attr_set = true;
    }

    init_kernel<<<1, 32>>>();
    main_kernel<<<GRID_X, NTHREADS, SMEM_BYTES>>>(F0, F0g, I0, I0R, I1, I1R, S0, S0g, S1, S1g);
    finalize_kernel<<<1, 1>>>((float*)d_out);
    (void)in_sizes; (void)n_in; (void)out_size;
}

// round 8
// speedup vs baseline: 1.3589x; 1.3589x over previous
#include <cuda_runtime.h>
#include <math.h>

#define FULL_MASK 0xFFFFFFFFu

// ---------------- problem constants ----------------
constexpr int DIM = 128;
constexpr int VOX = DIM * DIM * DIM;          // 2,097,152 per volume
constexpr double OMEGA_F = 12582912.0;        // (2,3,128^3)
constexpr double OMEGA_I = 4194304.0;         // (2,1,128^3)

// ---------------- LCC tile geometry ----------------
constexpr int TX = 32, TY = 8, TZ = 8;        // interior tile
constexpr int LY = TY + 4, LZ = TZ + 4;       // 12, 12 (halo 2 each side)
constexpr int AROWS = LZ * LY;                // 144 rows of 36 (x with halo)
constexpr int ASTR = 37;                      // padded row stride (odd -> conflict-free)
constexpr int BSTR = 33;                      // padded 32-wide rows
constexpr int A_SZ = AROWS * ASTR;            // 5328
constexpr int B_SZ = AROWS * BSTR;            // 4752
constexpr int C_SZ = LZ * TY * BSTR;          // 3168
constexpr int SMEM_FLOATS = 2 * (A_SZ + B_SZ + C_SZ);   // 26496
constexpr int SMEM_BYTES  = SMEM_FLOATS * 4;            // 105984 -> 2 CTAs/SM

constexpr int NTHREADS = 512;                 // 2 CTAs/SM -> 32 warps/SM
constexpr int NWARPS   = NTHREADS / 32;       // 16

// grid: bundles of 11 blocks -> 8 LCC tiles + 3 streaming jobs
// LCC tiles: 4(x)*16(y)*16(z)*2 vol*2 pair = 4096 = 512*8
// streaming: 3 jobs * 512 blocks
constexpr int BUNDLES = 512;
constexpr int GRID_X = BUNDLES * 11;          // 5632
constexpr int RED_BLOCKS_PER_JOB = 512;

// accumulators (doubles), zero-initialized at load; finalize re-zeroes after use:
// [0]      sum (F0-F0g)^2
// [1..3]   pair0: sum dg*dp, sum dg^2, sum dp^2
// [4..6]   pair1: same
// [7],[8]  tversky0: sum g*p, sum (g+p)
// [9],[10] tversky1: same
// [11]     dummy sink
__device__ double g_acc[12];

__device__ __forceinline__ void block_reduce_add3(float a, float b, float c,
                                                  double* d0, double* d1, double* d2) {
    __shared__ float red[3][NWARPS];
    #pragma unroll
    for (int o = 16; o > 0; o >>= 1) {
        a += __shfl_down_sync(FULL_MASK, a, o);
        b += __shfl_down_sync(FULL_MASK, b, o);
        c += __shfl_down_sync(FULL_MASK, c, o);
    }
    int w = threadIdx.x >> 5, l = threadIdx.x & 31;
    if (l == 0) { red[0][w] = a; red[1][w] = b; red[2][w] = c; }
    __syncthreads();
    if (w == 0) {
        a = (l < NWARPS) ? red[0][l] : 0.f;
        b = (l < NWARPS) ? red[1][l] : 0.f;
        c = (l < NWARPS) ? red[2][l] : 0.f;
        #pragma unroll
        for (int o = NWARPS / 2; o > 0; o >>= 1) {
            a += __shfl_down_sync(FULL_MASK, a, o);
            b += __shfl_down_sync(FULL_MASK, b, o);
            c += __shfl_down_sync(FULL_MASK, c, o);
        }
        if (l == 0) {
            atomicAdd(d0, (double)a);
            atomicAdd(d1, (double)b);
            atomicAdd(d2, (double)c);
        }
    }
}

__global__ void __launch_bounds__(NTHREADS, 2)
main_kernel(const float* __restrict__ F0,  const float* __restrict__ F0g,
            const float* __restrict__ I0,  const float* __restrict__ I0R,
            const float* __restrict__ I1,  const float* __restrict__ I1R,
            const float* __restrict__ S0,  const float* __restrict__ S0g,
            const float* __restrict__ S1,  const float* __restrict__ S1g) {
    extern __shared__ float sm[];
    const int tid = threadIdx.x;
    const int bid = blockIdx.x;
    const int q = bid / 11;
    const int r = bid - q * 11;

    if (r < 8) {
        // ---------------- LCC tile block ----------------
        int tile = q * 8 + r;             // [0, 4096)
        int tx_ = tile & 3;  int t = tile >> 2;
        int ty_ = t & 15;    t >>= 4;
        int tz_ = t & 15;    t >>= 4;
        int vol  = t & 1;
        int pair = t >> 1;

        const float* gt = (pair == 0 ? I0  : I1)  + vol * VOX;
        const float* pr = (pair == 0 ? I0R : I1R) + vol * VOX;
        const int x0 = tx_ * TX, y0 = ty_ * TY, z0 = tz_ * TZ;

        float* Ag = sm;
        float* Ap = Ag + A_SZ;
        float* Bg = Ap + A_SZ;
        float* Bp = Bg + B_SZ;
        float* Cg = Bp + B_SZ;
        float* Cp = Cg + C_SZ;

        // ---- load tile + halo (zero padding outside volume) ----
        for (int i = tid; i < AROWS * 36; i += NTHREADS) {
            int k   = i % 36;
            int row = i / 36;
            int ly = row % LY, lz = row / LY;
            int gx = x0 + k - 2, gy = y0 + ly - 2, gz = z0 + lz - 2;
            float vg = 0.f, vp = 0.f;
            if ((unsigned)gx < 128u && (unsigned)gy < 128u && (unsigned)gz < 128u) {
                int idx = (gz * DIM + gy) * DIM + gx;
                vg = __ldg(gt + idx);
                vp = __ldg(pr + idx);
            }
            Ag[row * ASTR + k] = vg;
            Ap[row * ASTR + k] = vp;
        }
        __syncthreads();

        // ---- x-pass: 5-tap running sums, 144 rows x 2 half-rows = 288 items ----
        if (tid < 2 * AROWS) {
            const int row = tid >> 1;
            const int xs  = (tid & 1) * 16;     // half start
            const float* ag = Ag + row * ASTR;
            const float* ap = Ap + row * ASTR;
            float* bg = Bg + row * BSTR;
            float* bp = Bp + row * BSTR;
            float sg = ag[xs] + ag[xs + 1] + ag[xs + 2] + ag[xs + 3];
            float sp = ap[xs] + ap[xs + 1] + ap[xs + 2] + ap[xs + 3];
            #pragma unroll
            for (int j = 0; j < 16; j++) {
                int x = xs + j;
                sg += ag[x + 4]; sp += ap[x + 4];
                bg[x] = sg;      bp[x] = sp;
                sg -= ag[x];     sp -= ap[x];
            }
        }
        __syncthreads();

        // ---- y-pass: running sum down y for (z, x) columns (12*32 = 384 items) ----
        if (tid < LZ * TX) {
            int x = tid & 31, z = tid >> 5;
            const float* bg = Bg + z * LY * BSTR + x;
            const float* bp = Bp + z * LY * BSTR + x;
            float* cg = Cg + z * TY * BSTR + x;
            float* cp = Cp + z * TY * BSTR + x;
            float sg = bg[0] + bg[BSTR] + bg[2 * BSTR] + bg[3 * BSTR];
            float sp = bp[0] + bp[BSTR] + bp[2 * BSTR] + bp[3 * BSTR];
            #pragma unroll
            for (int y = 0; y < TY; y++) {
                sg += bg[(y + 4) * BSTR]; sp += bp[(y + 4) * BSTR];
                cg[y * BSTR] = sg;        cp[y * BSTR] = sp;
                sg -= bg[y * BSTR];       sp -= bp[y * BSTR];
            }
        }
        __syncthreads();

        // ---- z-pass + finalize: 512 threads <-> (dzh, dy, dx) = 2x8x32 ----
        {
            const int dx  = tid & 31;
            const int dy  = (tid >> 5) & 7;
            const int dz0 = (tid >> 8) * 4;     // 0 or 4
            const float* cg = Cg + dy * BSTR + dx;
            const float* cp = Cp + dy * BSTR + dx;
            constexpr int CZ = TY * BSTR;       // z stride in C
            float sg = cg[dz0 * CZ] + cg[(dz0 + 1) * CZ] + cg[(dz0 + 2) * CZ] + cg[(dz0 + 3) * CZ];
            float sp = cp[dz0 * CZ] + cp[(dz0 + 1) * CZ] + cp[(dz0 + 2) * CZ] + cp[(dz0 + 3) * CZ];
            float s_gp = 0.f, s_gg = 0.f, s_pp = 0.f;
            constexpr float INV125 = 1.0f / 125.0f;
            #pragma unroll
            for (int j = 0; j < 4; j++) {
                int dz = dz0 + j;
                sg += cg[(dz + 4) * CZ];
                sp += cp[(dz + 4) * CZ];
                int aidx = ((dz + 2) * LY + dy + 2) * ASTR + dx + 2;
                float og = Ag[aidx];
                float op = Ap[aidx];
                float dg = og - sg * INV125;
                float dp = op - sp * INV125;
                s_gp += dg * dp;
                s_gg += dg * dg;
                s_pp += dp * dp;
                sg -= cg[dz * CZ];
                sp -= cp[dz * CZ];
            }
            block_reduce_add3(s_gp, s_gg, s_pp,
                              &g_acc[1 + 3 * pair], &g_acc[2 + 3 * pair], &g_acc[3 + 3 * pair]);
        }
    } else {
        // ---------------- streaming reduction block ----------------
        int job = r - 8;             // 0: F L2, 1: tversky0, 2: tversky1
        int jb  = q;                 // [0, 512)
        const float4 *a4, *b4;
        int n4;
        if (job == 0) { a4 = (const float4*)F0; b4 = (const float4*)F0g; n4 = (6 * VOX) / 4; }
        else if (job == 1) { a4 = (const float4*)S0; b4 = (const float4*)S0g; n4 = (2 * VOX) / 4; }
        else { a4 = (const float4*)S1; b4 = (const float4*)S1g; n4 = (2 * VOX) / 4; }

        float acc1 = 0.f, acc2 = 0.f;
        const int stride = RED_BLOCKS_PER_JOB * NTHREADS;
        if (job == 0) {
            for (int i = jb * NTHREADS + tid; i < n4; i += stride) {
                float4 x = __ldg(a4 + i), y = __ldg(b4 + i);
                float d0 = x.x - y.x, d1 = x.y - y.y, d2 = x.z - y.z, d3 = x.w - y.w;
                acc1 += d0 * d0 + d1 * d1 + d2 * d2 + d3 * d3;
            }
            block_reduce_add3(acc1, 0.f, 0.f, &g_acc[0], &g_acc[11], &g_acc[11]);
        } else {
            for (int i = jb * NTHREADS + tid; i < n4; i += stride) {
                float4 x = __ldg(a4 + i), y = __ldg(b4 + i);
                acc1 += x.x * y.x + x.y * y.y + x.z * y.z + x.w * y.w;
                acc2 += (x.x + y.x) + (x.y + y.y) + (x.z + y.z) + (x.w + y.w);
            }
            block_reduce_add3(acc1, acc2, 0.f,
                              &g_acc[5 + 2 * job], &g_acc[6 + 2 * job], &g_acc[11]);
        }
    }
}

__global__ void finalize_kernel(float* __restrict__ out) {
    // read everything first
    double a[12];
    #pragma unroll
    for (int i = 0; i < 12; i++) a[i] = g_acc[i];

    double total = sqrt(a[0]) / OMEGA_F;                  // reg_field_loss
    #pragma unroll
    for (int p = 0; p < 2; p++) {                         // LAMBDA * lcc
        double num = a[1 + 3 * p]; num *= num;
        double den = a[2 + 3 * p] * a[3 + 3 * p];
        if (den < 1e-5) den = 1e-5;
        total += 10.0 * (-(num / den) / OMEGA_I);
    }
    #pragma unroll
    for (int t = 0; t < 2; t++) {                         // BETA * tversky
        double den = a[8 + 2 * t];
        if (den < 1e-5) den = 1e-5;
        total += 10.0 * (-(a[7 + 2 * t] / den));
    }
    out[0] = (float)total;

    // re-zero accumulators for the next graph replay (statics start at 0)
    #pragma unroll
    for (int i = 0; i < 12; i++) g_acc[i] = 0.0;
}

extern "C" void kernel_launch(void* const* d_in, const int* in_sizes, int n_in,
                              void* d_out, int out_size) {
    const float* F0  = (const float*)d_in[0];
    const float* F0g = (const float*)d_in[1];
    const float* I0  = (const float*)d_in[2];
    const float* I0R = (const float*)d_in[3];
    const float* I1  = (const float*)d_in[4];
    const float* I1R = (const float*)d_in[5];
    const float* S0  = (const float*)d_in[6];
    const float* S0g = (const float*)d_in[7];
    const float* S1  = (const float*)d_in[8];
    const float* S1g = (const float*)d_in[9];

    static bool attr_set = false;
    if (!attr_set) {
        cudaFuncSetAttribute(main_kernel, cudaFuncAttributeMaxDynamicSharedMemorySize, SMEM_BYTES);
        attr_set = true;
    }

    main_kernel<<<GRID_X, NTHREADS, SMEM_BYTES>>>(F0, F0g, I0, I0R, I1, I1R, S0, S0g, S1, S1g);
    finalize_kernel<<<1, 1>>>((float*)d_out);
    (void)in_sizes; (void)n_in; (void)out_size;
}